// round 1
// baseline (speedup 1.0000x reference)
#include <cuda_runtime.h>

#define FULL_MASK 0xffffffffu

struct C2 { float x, y; };

// ---- device scratch (no allocations allowed) ----
__device__ float g_wc[42];
__device__ float g_ws[42];
__device__ float g_bloch[8 * 676 * 3];   // [patch][X,Y,Z], patch = b*676 + pi*26 + pj

// Precompute cos/sin of shared weight half-angles once per launch.
__global__ void prep_w_kernel(const float* __restrict__ w) {
    int i = threadIdx.x;
    if (i < 42) {
        float s, c;
        sincosf(0.5f * w[i], &s, &c);
        g_wc[i] = c;
        g_ws[i] = s;
    }
}

// ============================================================================
// Warp-resident 9-qubit statevector: amp index = lane*16 + r
//   qubits 0..3  -> register bits (r)
//   qubits 4..8  -> lane bits (lane)
// ============================================================================

__device__ __forceinline__ void apply_ry(C2 a[16], int q, float c, float s, int lane) {
    if (q < 4) {
        const int tb = 1 << q;
        #pragma unroll
        for (int r0 = 0; r0 < 16; ++r0) {
            if (r0 & tb) continue;
            C2 a0 = a[r0], a1 = a[r0 | tb];
            a[r0]      = { c * a0.x - s * a1.x, c * a0.y - s * a1.y };
            a[r0 | tb] = { s * a0.x + c * a1.x, s * a0.y + c * a1.y };
        }
    } else {
        const int lm = 1 << (q - 4);
        const float sgn = (lane & lm) ? s : -s;
        #pragma unroll
        for (int r = 0; r < 16; ++r) {
            float px = __shfl_xor_sync(FULL_MASK, a[r].x, lm);
            float py = __shfl_xor_sync(FULL_MASK, a[r].y, lm);
            a[r] = { c * a[r].x + sgn * px, c * a[r].y + sgn * py };
        }
    }
}

__device__ __forceinline__ void apply_rz(C2 a[16], int q, float c, float s, int lane) {
    // bit=0: *(c - i s), bit=1: *(c + i s). Diagonal -> no communication.
    #pragma unroll
    for (int r = 0; r < 16; ++r) {
        int bit = ((lane * 16 + r) >> q) & 1;
        float ss = bit ? s : -s;
        C2 v = a[r];
        a[r] = { c * v.x - ss * v.y, c * v.y + ss * v.x };
    }
}

__device__ __forceinline__ void apply_cx(C2 a[16], int c, int t, int lane) {
    if (t < 4) {
        const int tb = 1 << t;
        #pragma unroll
        for (int r0 = 0; r0 < 16; ++r0) {
            if (r0 & tb) continue;
            int i0 = lane * 16 + r0;
            if ((i0 >> c) & 1) {
                C2 tmp = a[r0];
                a[r0] = a[r0 | tb];
                a[r0 | tb] = tmp;
            }
        }
    } else {
        const int lm = 1 << (t - 4);
        #pragma unroll
        for (int r = 0; r < 16; ++r) {
            float px = __shfl_xor_sync(FULL_MASK, a[r].x, lm);
            float py = __shfl_xor_sync(FULL_MASK, a[r].y, lm);
            if (((lane * 16 + r) >> c) & 1) a[r] = { px, py };
        }
    }
}

__device__ __forceinline__ void apply_crx(C2 a[16], int c, int t, float co, float si, int lane) {
    // On control=1 subspace: new = co*v + (-i*si)*partner ; (-i*si)*(x+iy) = (si*y, -si*x)
    if (t < 4) {
        const int tb = 1 << t;
        #pragma unroll
        for (int r0 = 0; r0 < 16; ++r0) {
            if (r0 & tb) continue;
            int i0 = lane * 16 + r0;
            if ((i0 >> c) & 1) {
                C2 t0 = a[r0], t1 = a[r0 | tb];
                a[r0]      = { co * t0.x + si * t1.y, co * t0.y - si * t1.x };
                a[r0 | tb] = { co * t1.x + si * t0.y, co * t1.y - si * t0.x };
            }
        }
    } else {
        const int lm = 1 << (t - 4);
        #pragma unroll
        for (int r = 0; r < 16; ++r) {
            float px = __shfl_xor_sync(FULL_MASK, a[r].x, lm);
            float py = __shfl_xor_sync(FULL_MASK, a[r].y, lm);
            if (((lane * 16 + r) >> c) & 1)
                a[r] = { co * a[r].x + si * py, co * a[r].y - si * px };
        }
    }
}

// ============================================================================
// Main QCNN kernel: one warp per 3x3 patch circuit
// ============================================================================
__global__ void __launch_bounds__(256)
qcnn_kernel(const float* __restrict__ x, int npatch) {
    const int warp = (blockIdx.x * blockDim.x + threadIdx.x) >> 5;
    const int lane = threadIdx.x & 31;
    if (warp >= npatch) return;   // warp-uniform (grid sized exactly), shuffles safe

    const int b   = warp / 676;
    const int rem = warp - b * 676;
    const int pi  = rem / 26;
    const int pj  = rem - pi * 26;
    const float* img = x + b * 784;   // (28,28)

    // |0...0>
    C2 a[16];
    #pragma unroll
    for (int r = 0; r < 16; ++r) a[r] = { 0.f, 0.f };
    if (lane == 0) a[0] = { 1.f, 0.f };

    // ---- input encoding: RY(pixel * pi) on q = di*3+dj ----
    const float HALF_PI = 1.57079632679489662f;
    #pragma unroll
    for (int q = 0; q < 9; ++q) {
        const int di = q / 3, dj = q % 3;
        float th = img[(pi + di) * 28 + (pj + dj)] * HALF_PI;  // theta/2
        float s, c;
        sincosf(th, &s, &c);
        apply_ry(a, q, c, s, lane);
    }

    // ---- conv1: RY, RZ on all 9, ring CX ----
    #pragma unroll
    for (int q = 0; q < 9; ++q) apply_ry(a, q, g_wc[q], g_ws[q], lane);
    #pragma unroll
    for (int q = 0; q < 9; ++q) apply_rz(a, q, g_wc[9 + q], g_ws[9 + q], lane);
    #pragma unroll
    for (int i = 0; i < 9; ++i) apply_cx(a, i, (i + 1) % 9, lane);

    // ---- pool1: 6 CRX ----
    apply_crx(a, 1, 0, g_wc[18], g_ws[18], lane);
    apply_crx(a, 2, 0, g_wc[19], g_ws[19], lane);
    apply_crx(a, 4, 3, g_wc[20], g_ws[20], lane);
    apply_crx(a, 5, 3, g_wc[21], g_ws[21], lane);
    apply_crx(a, 7, 6, g_wc[22], g_ws[22], lane);
    apply_crx(a, 8, 6, g_wc[23], g_ws[23], lane);

    // ---- conv2 on {0,3,6} ----
    apply_ry(a, 0, g_wc[24], g_ws[24], lane);
    apply_ry(a, 3, g_wc[25], g_ws[25], lane);
    apply_ry(a, 6, g_wc[26], g_ws[26], lane);
    apply_rz(a, 0, g_wc[27], g_ws[27], lane);
    apply_rz(a, 3, g_wc[28], g_ws[28], lane);
    apply_rz(a, 6, g_wc[29], g_ws[29], lane);
    apply_cx(a, 0, 3, lane);
    apply_cx(a, 3, 6, lane);
    apply_cx(a, 6, 0, lane);
    apply_ry(a, 0, g_wc[30], g_ws[30], lane);
    apply_rz(a, 3, g_wc[31], g_ws[31], lane);

    // ---- pool2 ----
    apply_crx(a, 3, 0, g_wc[32], g_ws[32], lane);
    apply_crx(a, 3, 6, g_wc[33], g_ws[33], lane);
    apply_ry(a, 0, g_wc[34], g_ws[34], lane);
    apply_ry(a, 6, g_wc[35], g_ws[35], lane);

    // ---- conv3 ----
    apply_ry(a, 0, g_wc[36], g_ws[36], lane);
    apply_ry(a, 6, g_wc[37], g_ws[37], lane);
    apply_cx(a, 0, 6, lane);
    apply_rz(a, 0, g_wc[38], g_ws[38], lane);
    apply_rz(a, 6, g_wc[39], g_ws[39], lane);

    // ---- pool3 ----
    apply_crx(a, 6, 0, g_wc[40], g_ws[40], lane);
    apply_ry(a, 0, g_wc[41], g_ws[41], lane);

    // ---- <X>,<Y>,<Z> on qubit 0 (register bit 0) ----
    float zr = 0.f, zi = 0.f, ez = 0.f;
    #pragma unroll
    for (int r0 = 0; r0 < 16; r0 += 2) {
        C2 a0 = a[r0], a1 = a[r0 + 1];
        zr += a0.x * a1.x + a0.y * a1.y;          // Re(conj(a0)*a1)
        zi += a0.x * a1.y - a0.y * a1.x;          // Im(conj(a0)*a1)
        ez += a0.x * a0.x + a0.y * a0.y - a1.x * a1.x - a1.y * a1.y;
    }
    #pragma unroll
    for (int off = 16; off; off >>= 1) {
        zr += __shfl_xor_sync(FULL_MASK, zr, off);
        zi += __shfl_xor_sync(FULL_MASK, zi, off);
        ez += __shfl_xor_sync(FULL_MASK, ez, off);
    }
    if (lane == 0) {
        g_bloch[warp * 3 + 0] = 2.f * zr;
        g_bloch[warp * 3 + 1] = 2.f * zi;
        g_bloch[warp * 3 + 2] = ez;
    }
}

// ============================================================================
// FC: out[b, cls] = feats[b,:] . fc_w[cls,:] + fc_b[cls]
// feats[b,k] == g_bloch[b*K + k] (patch-major X,Y,Z layout matches reference)
// ============================================================================
__global__ void fc_kernel(const float* __restrict__ fc_w, const float* __restrict__ fc_b,
                          float* __restrict__ out, int K, int ncls) {
    const int b   = blockIdx.x / ncls;
    const int cls = blockIdx.x - b * ncls;
    const float* f  = g_bloch + b * K;
    const float* wv = fc_w + cls * K;

    float acc = 0.f;
    for (int k = threadIdx.x; k < K; k += blockDim.x) acc += f[k] * wv[k];

    #pragma unroll
    for (int off = 16; off; off >>= 1) acc += __shfl_xor_sync(FULL_MASK, acc, off);

    __shared__ float sh[8];
    if ((threadIdx.x & 31) == 0) sh[threadIdx.x >> 5] = acc;
    __syncthreads();
    if (threadIdx.x == 0) {
        float t = 0.f;
        int nw = blockDim.x >> 5;
        for (int i = 0; i < nw; ++i) t += sh[i];
        out[b * ncls + cls] = t + fc_b[cls];
    }
}

// ============================================================================
extern "C" void kernel_launch(void* const* d_in, const int* in_sizes, int n_in,
                              void* d_out, int out_size) {
    const float* x    = (const float*)d_in[0];   // (B,1,28,28)
    const float* w    = (const float*)d_in[1];   // (42,)
    const float* fc_w = (const float*)d_in[2];   // (ncls, 2028)
    const float* fc_b = (const float*)d_in[3];   // (ncls,)
    float* out = (float*)d_out;

    const int B      = in_sizes[0] / (28 * 28);
    const int npatch = B * 26 * 26;              // 5408 for B=8
    const int ncls   = in_sizes[3];
    const int K      = in_sizes[2] / ncls;       // 2028

    prep_w_kernel<<<1, 64>>>(w);

    const int warps_per_block = 8;
    const int blocks = (npatch + warps_per_block - 1) / warps_per_block;
    qcnn_kernel<<<blocks, warps_per_block * 32>>>(x, npatch);

    fc_kernel<<<B * ncls, 128>>>(fc_w, fc_b, out, K, ncls);
}

// round 2
// speedup vs baseline: 1.8111x; 1.8111x over previous
#include <cuda_runtime.h>

#define FULL_MASK 0xffffffffu

// ---- device scratch (no allocations allowed) ----
__device__ float g_bloch[8 * 676 * 3];   // [patch][X,Y,Z]

// ============================================================================
// Packed f32x2 helpers (sm_103a: FFMA2 only reachable via PTX fma.rn.f32x2)
// ============================================================================
__device__ __forceinline__ float2 f2fma(float2 a, float2 b, float2 c) {
    float2 d;
    asm("fma.rn.f32x2 %0, %1, %2, %3;"
        : "=l"(*reinterpret_cast<unsigned long long*>(&d))
        : "l"(*reinterpret_cast<unsigned long long*>(&a)),
          "l"(*reinterpret_cast<unsigned long long*>(&b)),
          "l"(*reinterpret_cast<unsigned long long*>(&c)));
    return d;
}
__device__ __forceinline__ float2 f2mul(float2 a, float2 b) {
    float2 d;
    asm("mul.rn.f32x2 %0, %1, %2;"
        : "=l"(*reinterpret_cast<unsigned long long*>(&d))
        : "l"(*reinterpret_cast<unsigned long long*>(&a)),
          "l"(*reinterpret_cast<unsigned long long*>(&b)));
    return d;
}
__device__ __forceinline__ float2 cmul(float2 a, float2 b) {
    return { a.x * b.x - a.y * b.y, a.x * b.y + a.y * b.x };
}

// ============================================================================
// Layout: amp(lane, r) ; register bits r[0..3] = qubits {0,1,3,6}
//                        lane bits  [0..4]    = qubits {2,4,5,7,8}
// ============================================================================

template<int TB>
__device__ __forceinline__ void ry_reg(float2* a, float c, float s) {
    const float2 c2 = { c, c }, s2 = { s, s }, ns2 = { -s, -s };
    #pragma unroll
    for (int r0 = 0; r0 < 16; ++r0) {
        if (r0 & TB) continue;
        float2 a0 = a[r0], a1 = a[r0 | TB];
        a[r0]      = f2fma(a1, ns2, f2mul(a0, c2));
        a[r0 | TB] = f2fma(a0, s2,  f2mul(a1, c2));
    }
}

template<int LM>
__device__ __forceinline__ void ry_lane(float2* a, float c, float s, int lane) {
    const float2 c2 = { c, c };
    const float sg = (lane & LM) ? s : -s;
    const float2 sg2 = { sg, sg };
    #pragma unroll
    for (int r = 0; r < 16; ++r) {
        float2 p;
        p.x = __shfl_xor_sync(FULL_MASK, a[r].x, LM);
        p.y = __shfl_xor_sync(FULL_MASK, a[r].y, LM);
        a[r] = f2fma(p, sg2, f2mul(a[r], c2));
    }
}

template<int CB, int TB>
__device__ __forceinline__ void cx_rr(float2* a) {
    #pragma unroll
    for (int r0 = 0; r0 < 16; ++r0) {
        if ((r0 & CB) && !(r0 & TB)) {
            float2 t = a[r0]; a[r0] = a[r0 | TB]; a[r0 | TB] = t;
        }
    }
}

template<int CB, int LM>
__device__ __forceinline__ void cx_rl(float2* a) {
    #pragma unroll
    for (int r = 0; r < 16; ++r) {
        if (r & CB) {   // compile-time: only 8 registers shuffle
            float2 p;
            p.x = __shfl_xor_sync(FULL_MASK, a[r].x, LM);
            p.y = __shfl_xor_sync(FULL_MASK, a[r].y, LM);
            a[r] = p;
        }
    }
}

template<int LMC, int TB>
__device__ __forceinline__ void cx_lr(float2* a, int lane) {
    const bool p = (lane & LMC) != 0;
    #pragma unroll
    for (int r0 = 0; r0 < 16; ++r0) {
        if (r0 & TB) continue;
        if (p) { float2 t = a[r0]; a[r0] = a[r0 | TB]; a[r0 | TB] = t; }
    }
}

template<int LMC, int LMT>
__device__ __forceinline__ void cx_ll(float2* a, int lane) {
    const bool p = (lane & LMC) != 0;
    #pragma unroll
    for (int r = 0; r < 16; ++r) {
        float px = __shfl_xor_sync(FULL_MASK, a[r].x, LMT);
        float py = __shfl_xor_sync(FULL_MASK, a[r].y, LMT);
        if (p) a[r] = { px, py };
    }
}

// CRX on control=1 subspace: n0 = co*t0 + si*(t1.y, -t1.x); n1 = co*t1 + si*(t0.y, -t0.x)
template<int CB, int TB>
__device__ __forceinline__ void crx_rr(float2* a, float co, float si) {
    #pragma unroll
    for (int r0 = 0; r0 < 16; ++r0) {
        if ((r0 & CB) && !(r0 & TB)) {
            float2 t0 = a[r0], t1 = a[r0 | TB];
            a[r0]      = { co * t0.x + si * t1.y, co * t0.y - si * t1.x };
            a[r0 | TB] = { co * t1.x + si * t0.y, co * t1.y - si * t0.x };
        }
    }
}

template<int LMC, int TB>
__device__ __forceinline__ void crx_lr(float2* a, float co, float si, int lane) {
    const bool p = (lane & LMC) != 0;
    #pragma unroll
    for (int r0 = 0; r0 < 16; ++r0) {
        if (r0 & TB) continue;
        float2 t0 = a[r0], t1 = a[r0 | TB];
        float2 n0 = { co * t0.x + si * t1.y, co * t0.y - si * t1.x };
        float2 n1 = { co * t1.x + si * t0.y, co * t1.y - si * t0.x };
        if (p) { a[r0] = n0; a[r0 | TB] = n1; }
    }
}

// ============================================================================
// Main QCNN kernel: one warp per 3x3 patch; weight-prep fused in block prologue
// ============================================================================
__global__ void __launch_bounds__(256)
qcnn_kernel(const float* __restrict__ x, const float* __restrict__ w, int npatch) {
    __shared__ float  s_wc[42], s_ws[42], s_wh[9];
    __shared__ float2 s_d1r[16], s_d1l[32], s_d2[16];
    __shared__ float2 s_mry0, s_mry6;

    const int tid = threadIdx.x;

    // ---- per-block weight prep (shared across 8 warps) ----
    if (tid < 42) {
        float s, c;
        sincosf(0.5f * w[tid], &s, &c);
        s_wc[tid] = c; s_ws[tid] = s;
    }
    if (tid < 9) s_wh[tid] = 0.5f * w[tid];
    if (tid >= 64 && tid < 80) {            // conv1 RZ diag, register qubits {0,1,3,6}
        int r = tid - 64;
        float ang = 0.5f * (((r & 1) ? w[9]  : -w[9])  + ((r & 2) ? w[10] : -w[10])
                          + ((r & 4) ? w[12] : -w[12]) + ((r & 8) ? w[15] : -w[15]));
        float s, c; sincosf(ang, &s, &c);
        s_d1r[r] = { c, s };
    }
    if (tid >= 96 && tid < 128) {           // conv1 RZ diag, lane qubits {2,4,5,7,8}
        int l = tid - 96;
        float ang = 0.5f * (((l & 1)  ? w[11] : -w[11]) + ((l & 2)  ? w[13] : -w[13])
                          + ((l & 4)  ? w[14] : -w[14]) + ((l & 8)  ? w[16] : -w[16])
                          + ((l & 16) ? w[17] : -w[17]));
        float s, c; sincosf(ang, &s, &c);
        s_d1l[l] = { c, s };
    }
    if (tid >= 128 && tid < 144) {          // conv2 RZ diag on {0->bit0, 3->bit2, 6->bit3}
        int r = tid - 128;
        float ang = 0.5f * (((r & 1) ? w[27] : -w[27]) + ((r & 4) ? w[28] : -w[28])
                          + ((r & 8) ? w[29] : -w[29]));
        float s, c; sincosf(ang, &s, &c);
        s_d2[r] = { c, s };
    }
    if (tid == 160) { float s, c; sincosf(0.5f * (w[34] + w[36]), &s, &c); s_mry0 = { c, s }; }
    if (tid == 161) { float s, c; sincosf(0.5f * (w[35] + w[37]), &s, &c); s_mry6 = { c, s }; }
    __syncthreads();

    const int warp   = (blockIdx.x * blockDim.x + tid) >> 5;
    const int lane   = tid & 31;
    const bool active = warp < npatch;
    const int wp = active ? warp : 0;

    const int b   = wp / 676;
    const int rem = wp - b * 676;
    const int pi  = rem / 26;
    const int pj  = rem - pi * 26;
    const float* img = x + b * 784;

    // |0...0>
    float2 a[16];
    #pragma unroll
    for (int r = 0; r < 16; ++r) a[r] = { 0.f, 0.f };
    if (lane == 0) a[0] = { 1.f, 0.f };

    // ---- merged (encoding + conv1) RY: half-angle = px*pi/2 + w[q]/2 ----
    const float HALF_PI = 1.57079632679489662f;
    float th, s, c;
    th = img[(pi + 0) * 28 + (pj + 0)] * HALF_PI + s_wh[0]; __sincosf(th, &s, &c); ry_reg<1>(a, c, s);
    th = img[(pi + 0) * 28 + (pj + 1)] * HALF_PI + s_wh[1]; __sincosf(th, &s, &c); ry_reg<2>(a, c, s);
    th = img[(pi + 0) * 28 + (pj + 2)] * HALF_PI + s_wh[2]; __sincosf(th, &s, &c); ry_lane<1>(a, c, s, lane);
    th = img[(pi + 1) * 28 + (pj + 0)] * HALF_PI + s_wh[3]; __sincosf(th, &s, &c); ry_reg<4>(a, c, s);
    th = img[(pi + 1) * 28 + (pj + 1)] * HALF_PI + s_wh[4]; __sincosf(th, &s, &c); ry_lane<2>(a, c, s, lane);
    th = img[(pi + 1) * 28 + (pj + 2)] * HALF_PI + s_wh[5]; __sincosf(th, &s, &c); ry_lane<4>(a, c, s, lane);
    th = img[(pi + 2) * 28 + (pj + 0)] * HALF_PI + s_wh[6]; __sincosf(th, &s, &c); ry_reg<8>(a, c, s);
    th = img[(pi + 2) * 28 + (pj + 1)] * HALF_PI + s_wh[7]; __sincosf(th, &s, &c); ry_lane<8>(a, c, s, lane);
    th = img[(pi + 2) * 28 + (pj + 2)] * HALF_PI + s_wh[8]; __sincosf(th, &s, &c); ry_lane<16>(a, c, s, lane);

    // ---- conv1 RZ layer as one precomputed diagonal ----
    {
        const float2 dl = s_d1l[lane];
        #pragma unroll
        for (int r = 0; r < 16; ++r) a[r] = cmul(a[r], cmul(dl, s_d1r[r]));
    }

    // ---- ring CX (q -> q+1 mod 9) under the remap ----
    cx_rr<1, 2>(a);            // (0,1)
    cx_rl<2, 1>(a);            // (1,2)
    cx_lr<1, 4>(a, lane);      // (2,3)
    cx_rl<4, 2>(a);            // (3,4)
    cx_ll<2, 4>(a, lane);      // (4,5)
    cx_lr<4, 8>(a, lane);      // (5,6)
    cx_rl<8, 8>(a);            // (6,7)
    cx_ll<8, 16>(a, lane);     // (7,8)
    cx_lr<16, 1>(a, lane);     // (8,0)

    // ---- pool1: 6 CRX (targets all in registers after remap) ----
    crx_rr<2, 1>(a, s_wc[18], s_ws[18]);          // (1,0)
    crx_lr<1, 1>(a, s_wc[19], s_ws[19], lane);    // (2,0)
    crx_lr<2, 4>(a, s_wc[20], s_ws[20], lane);    // (4,3)
    crx_lr<4, 4>(a, s_wc[21], s_ws[21], lane);    // (5,3)
    crx_lr<8, 8>(a, s_wc[22], s_ws[22], lane);    // (7,6)
    crx_lr<16, 8>(a, s_wc[23], s_ws[23], lane);   // (8,6)

    // ---- conv2 on {0,3,6}: all register-local ----
    ry_reg<1>(a, s_wc[24], s_ws[24]);
    ry_reg<4>(a, s_wc[25], s_ws[25]);
    ry_reg<8>(a, s_wc[26], s_ws[26]);
    {   // conv2 RZ diag
        #pragma unroll
        for (int r = 0; r < 16; ++r) a[r] = cmul(a[r], s_d2[r]);
    }
    cx_rr<1, 4>(a);            // (0,3)
    cx_rr<4, 8>(a);            // (3,6)
    cx_rr<8, 1>(a);            // (6,0)
    ry_reg<1>(a, s_wc[30], s_ws[30]);
    // RZ(3, w31) dropped: commutes through to the end, unobservable on q0.

    // ---- pool2 CRX ----
    crx_rr<4, 1>(a, s_wc[32], s_ws[32]);   // (3,0)
    crx_rr<4, 8>(a, s_wc[33], s_ws[33]);   // (3,6)
    // merged RY(0, w34+w36), RY(6, w35+w37)
    ry_reg<1>(a, s_mry0.x, s_mry0.y);
    ry_reg<8>(a, s_mry6.x, s_mry6.y);

    // ---- conv3 ----
    cx_rr<1, 8>(a);            // (0,6)
    {   // RZ(0, w38): diag on register bit 0
        const float cz = s_wc[38], sz = s_ws[38];
        #pragma unroll
        for (int r = 0; r < 16; ++r) {
            float d = (r & 1) ? sz : -sz;
            float2 v = a[r];
            a[r] = { cz * v.x - d * v.y, cz * v.y + d * v.x };
        }
    }
    // RZ(6, w39) dropped: commutes through to the end, unobservable on q0.

    // ---- pool3 ----
    crx_rr<8, 1>(a, s_wc[40], s_ws[40]);   // (6,0)
    ry_reg<1>(a, s_wc[41], s_ws[41]);

    // ---- <X>,<Y>,<Z> on qubit 0 (register bit 0) ----
    float zr = 0.f, zi = 0.f, ez = 0.f;
    #pragma unroll
    for (int r0 = 0; r0 < 16; r0 += 2) {
        float2 a0 = a[r0], a1 = a[r0 + 1];
        zr += a0.x * a1.x + a0.y * a1.y;
        zi += a0.x * a1.y - a0.y * a1.x;
        ez += a0.x * a0.x + a0.y * a0.y - a1.x * a1.x - a1.y * a1.y;
    }
    #pragma unroll
    for (int off = 16; off; off >>= 1) {
        zr += __shfl_xor_sync(FULL_MASK, zr, off);
        zi += __shfl_xor_sync(FULL_MASK, zi, off);
        ez += __shfl_xor_sync(FULL_MASK, ez, off);
    }
    if (active && lane == 0) {
        g_bloch[warp * 3 + 0] = 2.f * zr;
        g_bloch[warp * 3 + 1] = 2.f * zi;
        g_bloch[warp * 3 + 2] = ez;
    }
}

// ============================================================================
// FC: out[b, cls] = feats[b,:] . fc_w[cls,:] + fc_b[cls]   (vectorized float4)
// ============================================================================
__global__ void fc_kernel(const float* __restrict__ fc_w, const float* __restrict__ fc_b,
                          float* __restrict__ out, int K, int ncls) {
    const int b   = blockIdx.x / ncls;
    const int cls = blockIdx.x - b * ncls;
    const float* f  = g_bloch + b * K;
    const float* wv = fc_w + cls * K;

    float acc = 0.f;
    if ((K & 3) == 0) {
        const float4* f4 = (const float4*)f;
        const float4* w4 = (const float4*)wv;
        const int K4 = K >> 2;
        for (int k = threadIdx.x; k < K4; k += blockDim.x) {
            float4 a = f4[k], bb = w4[k];
            acc += a.x * bb.x + a.y * bb.y + a.z * bb.z + a.w * bb.w;
        }
    } else {
        for (int k = threadIdx.x; k < K; k += blockDim.x) acc += f[k] * wv[k];
    }

    #pragma unroll
    for (int off = 16; off; off >>= 1) acc += __shfl_xor_sync(FULL_MASK, acc, off);

    __shared__ float sh[8];
    if ((threadIdx.x & 31) == 0) sh[threadIdx.x >> 5] = acc;
    __syncthreads();
    if (threadIdx.x == 0) {
        float t = 0.f;
        int nw = blockDim.x >> 5;
        for (int i = 0; i < nw; ++i) t += sh[i];
        out[b * ncls + cls] = t + fc_b[cls];
    }
}

// ============================================================================
extern "C" void kernel_launch(void* const* d_in, const int* in_sizes, int n_in,
                              void* d_out, int out_size) {
    const float* x    = (const float*)d_in[0];   // (B,1,28,28)
    const float* w    = (const float*)d_in[1];   // (42,)
    const float* fc_w = (const float*)d_in[2];   // (ncls, K)
    const float* fc_b = (const float*)d_in[3];   // (ncls,)
    float* out = (float*)d_out;

    const int B      = in_sizes[0] / (28 * 28);
    const int npatch = B * 26 * 26;
    const int ncls   = in_sizes[3];
    const int K      = in_sizes[2] / ncls;

    const int warps_per_block = 8;
    const int blocks = (npatch + warps_per_block - 1) / warps_per_block;
    qcnn_kernel<<<blocks, warps_per_block * 32>>>(x, w, npatch);

    fc_kernel<<<B * ncls, 128>>>(fc_w, fc_b, out, K, ncls);
}

// round 3
// speedup vs baseline: 2.4697x; 1.3636x over previous
#include <cuda_runtime.h>

#define FULL_MASK 0xffffffffu

// ---- device scratch / precomputed tables (no allocations allowed) ----
__device__ float  g_wc[42], g_ws[42];   // cos/sin of weight half-angles
__device__ float  g_wh[9];              // w[q]/2 for merged encoding
__device__ float2 g_d1r[16];            // conv1 RZ diagonal over register bits {q0,q1,q3,q6}
__device__ float2 g_d1l[32];            // conv1 RZ diagonal over lane bits {q2,q4,q5,q7,q8}
__device__ float2 g_d2[16];             // conv2 RZ diagonal over reg bits {q0:b0, q3:b2, q6:b3}
__device__ float2 g_mry0, g_mry6;       // merged RY(w34+w36), RY(w35+w37)

// ============================================================================
// Init kernel (1 block): weight trig tables + out = fc_b broadcast
// ============================================================================
__global__ void init_kernel(const float* __restrict__ w,
                            const float* __restrict__ fc_b,
                            float* __restrict__ out, int ncls, int nout) {
    const int tid = threadIdx.x;
    if (tid < 42) {
        float s, c; sincosf(0.5f * w[tid], &s, &c);
        g_wc[tid] = c; g_ws[tid] = s;
    }
    if (tid < 9) g_wh[tid] = 0.5f * w[tid];
    if (tid >= 64 && tid < 80) {            // conv1 RZ diag, register qubits {0,1,3,6}
        int r = tid - 64;
        float ang = 0.5f * (((r & 1) ? w[9]  : -w[9])  + ((r & 2) ? w[10] : -w[10])
                          + ((r & 4) ? w[12] : -w[12]) + ((r & 8) ? w[15] : -w[15]));
        float s, c; sincosf(ang, &s, &c);
        g_d1r[r] = { c, s };
    }
    if (tid >= 96 && tid < 128) {           // conv1 RZ diag, lane qubits {2,4,5,7,8}
        int l = tid - 96;
        float ang = 0.5f * (((l & 1)  ? w[11] : -w[11]) + ((l & 2)  ? w[13] : -w[13])
                          + ((l & 4)  ? w[14] : -w[14]) + ((l & 8)  ? w[16] : -w[16])
                          + ((l & 16) ? w[17] : -w[17]));
        float s, c; sincosf(ang, &s, &c);
        g_d1l[l] = { c, s };
    }
    if (tid >= 128 && tid < 144) {          // conv2 RZ diag on {0->bit0, 3->bit2, 6->bit3}
        int r = tid - 128;
        float ang = 0.5f * (((r & 1) ? w[27] : -w[27]) + ((r & 4) ? w[28] : -w[28])
                          + ((r & 8) ? w[29] : -w[29]));
        float s, c; sincosf(ang, &s, &c);
        g_d2[r] = { c, s };
    }
    if (tid == 160) { float s, c; sincosf(0.5f * (w[34] + w[36]), &s, &c); g_mry0 = { c, s }; }
    if (tid == 161) { float s, c; sincosf(0.5f * (w[35] + w[37]), &s, &c); g_mry6 = { c, s }; }
    // out[b*ncls+cls] = fc_b[cls]
    for (int i = tid; i < nout; i += blockDim.x) out[i] = fc_b[i % ncls];
}

// ============================================================================
// Packed f32x2 helpers
// ============================================================================
__device__ __forceinline__ float2 f2fma(float2 a, float2 b, float2 c) {
    float2 d;
    asm("fma.rn.f32x2 %0, %1, %2, %3;"
        : "=l"(*reinterpret_cast<unsigned long long*>(&d))
        : "l"(*reinterpret_cast<unsigned long long*>(&a)),
          "l"(*reinterpret_cast<unsigned long long*>(&b)),
          "l"(*reinterpret_cast<unsigned long long*>(&c)));
    return d;
}
__device__ __forceinline__ float2 f2mul(float2 a, float2 b) {
    float2 d;
    asm("mul.rn.f32x2 %0, %1, %2;"
        : "=l"(*reinterpret_cast<unsigned long long*>(&d))
        : "l"(*reinterpret_cast<unsigned long long*>(&a)),
          "l"(*reinterpret_cast<unsigned long long*>(&b)));
    return d;
}
__device__ __forceinline__ float2 cmul(float2 a, float2 b) {
    return { a.x * b.x - a.y * b.y, a.x * b.y + a.y * b.x };
}

// ============================================================================
// Layout: amp(lane, r) ; register bits r[0..3] = qubits {0,1,3,6}
//                        lane bits  [0..4]    = qubits {2,4,5,7,8}
// ============================================================================

template<int TB>
__device__ __forceinline__ void ry_reg(float2* a, float c, float s) {
    const float2 c2 = { c, c }, s2 = { s, s }, ns2 = { -s, -s };
    #pragma unroll
    for (int r0 = 0; r0 < 16; ++r0) {
        if (r0 & TB) continue;
        float2 a0 = a[r0], a1 = a[r0 | TB];
        a[r0]      = f2fma(a1, ns2, f2mul(a0, c2));
        a[r0 | TB] = f2fma(a0, s2,  f2mul(a1, c2));
    }
}

template<int CB, int TB>
__device__ __forceinline__ void cx_rr(float2* a) {   // pure register permutation
    #pragma unroll
    for (int r0 = 0; r0 < 16; ++r0) {
        if ((r0 & CB) && !(r0 & TB)) {
            float2 t = a[r0]; a[r0] = a[r0 | TB]; a[r0 | TB] = t;
        }
    }
}

template<int CB, int LM>
__device__ __forceinline__ void cx_rl(float2* a) {   // reg control, lane target: 8 regs shuffle
    #pragma unroll
    for (int r = 0; r < 16; ++r) {
        if (r & CB) {
            float2 p;
            p.x = __shfl_xor_sync(FULL_MASK, a[r].x, LM);
            p.y = __shfl_xor_sync(FULL_MASK, a[r].y, LM);
            a[r] = p;
        }
    }
}

template<int LMC, int TB>
__device__ __forceinline__ void cx_lr(float2* a, int lane) {  // lane control, reg target: selects
    const bool p = (lane & LMC) != 0;
    #pragma unroll
    for (int r0 = 0; r0 < 16; ++r0) {
        if (r0 & TB) continue;
        if (p) { float2 t = a[r0]; a[r0] = a[r0 | TB]; a[r0 | TB] = t; }
    }
}

template<int LMC, int LMT>
__device__ __forceinline__ void cx_ll(float2* a, int lane) {
    const bool p = (lane & LMC) != 0;
    #pragma unroll
    for (int r = 0; r < 16; ++r) {
        float px = __shfl_xor_sync(FULL_MASK, a[r].x, LMT);
        float py = __shfl_xor_sync(FULL_MASK, a[r].y, LMT);
        if (p) a[r] = { px, py };
    }
}

// CRX on control=1 subspace: n0 = co*t0 + si*(t1.y, -t1.x); n1 = co*t1 + si*(t0.y, -t0.x)
template<int CB, int TB>
__device__ __forceinline__ void crx_rr(float2* a, float co, float si) {
    #pragma unroll
    for (int r0 = 0; r0 < 16; ++r0) {
        if ((r0 & CB) && !(r0 & TB)) {
            float2 t0 = a[r0], t1 = a[r0 | TB];
            a[r0]      = { co * t0.x + si * t1.y, co * t0.y - si * t1.x };
            a[r0 | TB] = { co * t1.x + si * t0.y, co * t1.y - si * t0.x };
        }
    }
}

// lane control: fold predicate into coefficients (identity = co 1, si 0), apply unconditionally
template<int LMC, int TB>
__device__ __forceinline__ void crx_lr(float2* a, float co, float si, int lane) {
    const bool p = (lane & LMC) != 0;
    const float cp = p ? co : 1.0f;
    const float sp = p ? si : 0.0f;
    #pragma unroll
    for (int r0 = 0; r0 < 16; ++r0) {
        if (r0 & TB) continue;
        float2 t0 = a[r0], t1 = a[r0 | TB];
        a[r0]      = { cp * t0.x + sp * t1.y, cp * t0.y - sp * t1.x };
        a[r0 | TB] = { cp * t1.x + sp * t0.y, cp * t1.y - sp * t0.x };
    }
}

// ============================================================================
// QCNN + fused FC: one warp per patch, 4 warps/block (block uniform in image b)
// ============================================================================
__global__ void __launch_bounds__(128)
qcnn_kernel(const float* __restrict__ x, const float* __restrict__ fc_w,
            float* __restrict__ out, int npatch, int K, int ncls) {
    __shared__ float s_acc[32];

    const int tid  = threadIdx.x;
    const int lane = tid & 31;
    if (tid < 32) s_acc[tid] = 0.f;
    __syncthreads();

    const int warp   = (blockIdx.x * blockDim.x + tid) >> 5;
    const bool active = warp < npatch;
    const int wp  = active ? warp : 0;
    const int b   = wp / 676;
    const int rem = wp - b * 676;
    const int pi  = rem / 26;
    const int pj  = rem - pi * 26;
    const float* img = x + b * 784;

    // ---- product state: merged (encoding + conv1) RY, then conv1 RZ diagonal ----
    const float HALF_PI = 1.57079632679489662f;
    float cr[4], sr[4], cl[5], sl[5];
    // register qubits: q0(0,0) q1(0,1) q3(1,0) q6(2,0)
    __sincosf(img[(pi + 0) * 28 + (pj + 0)] * HALF_PI + g_wh[0], &sr[0], &cr[0]);
    __sincosf(img[(pi + 0) * 28 + (pj + 1)] * HALF_PI + g_wh[1], &sr[1], &cr[1]);
    __sincosf(img[(pi + 1) * 28 + (pj + 0)] * HALF_PI + g_wh[3], &sr[2], &cr[2]);
    __sincosf(img[(pi + 2) * 28 + (pj + 0)] * HALF_PI + g_wh[6], &sr[3], &cr[3]);
    // lane qubits: q2(0,2) q4(1,1) q5(1,2) q7(2,1) q8(2,2)
    __sincosf(img[(pi + 0) * 28 + (pj + 2)] * HALF_PI + g_wh[2], &sl[0], &cl[0]);
    __sincosf(img[(pi + 1) * 28 + (pj + 1)] * HALF_PI + g_wh[4], &sl[1], &cl[1]);
    __sincosf(img[(pi + 1) * 28 + (pj + 2)] * HALF_PI + g_wh[5], &sl[2], &cl[2]);
    __sincosf(img[(pi + 2) * 28 + (pj + 1)] * HALF_PI + g_wh[7], &sl[3], &cl[3]);
    __sincosf(img[(pi + 2) * 28 + (pj + 2)] * HALF_PI + g_wh[8], &sl[4], &cl[4]);

    float Lp = ((lane & 1)  ? sl[0] : cl[0]) * ((lane & 2)  ? sl[1] : cl[1]);
    Lp *= ((lane & 4)  ? sl[2] : cl[2]);
    Lp *= ((lane & 8)  ? sl[3] : cl[3]);
    Lp *= ((lane & 16) ? sl[4] : cl[4]);

    const float p01[4] = { cr[0]*cr[1], sr[0]*cr[1], cr[0]*sr[1], sr[0]*sr[1] };
    const float p23[4] = { cr[2]*cr[3], sr[2]*cr[3], cr[2]*sr[3], sr[2]*sr[3] };

    const float2 dl = g_d1l[lane];
    const float2 LD = { Lp * dl.x, Lp * dl.y };

    float2 a[16];
    #pragma unroll
    for (int r = 0; r < 16; ++r) {
        const float rp = p01[r & 3] * p23[r >> 2];
        const float2 d = g_d1r[r];
        a[r] = { rp * (LD.x * d.x - LD.y * d.y), rp * (LD.x * d.y + LD.y * d.x) };
    }

    // ---- ring CX (q -> q+1 mod 9) under the remap ----
    cx_rr<1, 2>(a);            // (0,1)
    cx_rl<2, 1>(a);            // (1,2)
    cx_lr<1, 4>(a, lane);      // (2,3)
    cx_rl<4, 2>(a);            // (3,4)
    cx_ll<2, 4>(a, lane);      // (4,5)
    cx_lr<4, 8>(a, lane);      // (5,6)
    cx_rl<8, 8>(a);            // (6,7)
    cx_ll<8, 16>(a, lane);     // (7,8)
    cx_lr<16, 1>(a, lane);     // (8,0)

    // ---- pool1: 6 CRX ----
    crx_rr<2, 1>(a, g_wc[18], g_ws[18]);          // (1,0)
    crx_lr<1, 1>(a, g_wc[19], g_ws[19], lane);    // (2,0)
    crx_lr<2, 4>(a, g_wc[20], g_ws[20], lane);    // (4,3)
    crx_lr<4, 4>(a, g_wc[21], g_ws[21], lane);    // (5,3)
    crx_lr<8, 8>(a, g_wc[22], g_ws[22], lane);    // (7,6)
    crx_lr<16, 8>(a, g_wc[23], g_ws[23], lane);   // (8,6)

    // ---- conv2 on {0,3,6}: register-local ----
    ry_reg<1>(a, g_wc[24], g_ws[24]);
    ry_reg<4>(a, g_wc[25], g_ws[25]);
    ry_reg<8>(a, g_wc[26], g_ws[26]);
    #pragma unroll
    for (int r = 0; r < 16; ++r) a[r] = cmul(a[r], g_d2[r]);
    cx_rr<1, 4>(a);            // (0,3)
    cx_rr<4, 8>(a);            // (3,6)
    cx_rr<8, 1>(a);            // (6,0)
    ry_reg<1>(a, g_wc[30], g_ws[30]);
    // RZ(3, w31) dropped: commutes to the end, unobservable on q0.

    // ---- pool2 ----
    crx_rr<4, 1>(a, g_wc[32], g_ws[32]);   // (3,0)
    crx_rr<4, 8>(a, g_wc[33], g_ws[33]);   // (3,6)
    {
        const float2 m0 = g_mry0; ry_reg<1>(a, m0.x, m0.y);   // RY(0, w34+w36)
        const float2 m6 = g_mry6; ry_reg<8>(a, m6.x, m6.y);   // RY(6, w35+w37)
    }

    // ---- conv3 ----
    cx_rr<1, 8>(a);            // (0,6)
    {   // RZ(0, w38) on register bit 0
        const float cz = g_wc[38], sz = g_ws[38];
        #pragma unroll
        for (int r = 0; r < 16; ++r) {
            const float d = (r & 1) ? sz : -sz;
            const float2 v = a[r];
            a[r] = { cz * v.x - d * v.y, cz * v.y + d * v.x };
        }
    }
    // RZ(6, w39) dropped.

    // ---- pool3 ----
    crx_rr<8, 1>(a, g_wc[40], g_ws[40]);   // (6,0)
    ry_reg<1>(a, g_wc[41], g_ws[41]);

    // ---- <X>,<Y>,<Z> on qubit 0 (register bit 0) ----
    float zr = 0.f, zi = 0.f, ez = 0.f;
    #pragma unroll
    for (int r0 = 0; r0 < 16; r0 += 2) {
        float2 a0 = a[r0], a1 = a[r0 + 1];
        zr += a0.x * a1.x + a0.y * a1.y;
        zi += a0.x * a1.y - a0.y * a1.x;
        ez += a0.x * a0.x + a0.y * a0.y - a1.x * a1.x - a1.y * a1.y;
    }
    #pragma unroll
    for (int off = 16; off; off >>= 1) {
        zr += __shfl_xor_sync(FULL_MASK, zr, off);
        zi += __shfl_xor_sync(FULL_MASK, zi, off);
        ez += __shfl_xor_sync(FULL_MASK, ez, off);
    }

    // ---- fused FC: lanes 0..ncls-1 accumulate class partials into smem ----
    if (active && lane < ncls) {
        const float* wrow = fc_w + lane * K + rem * 3;
        const float partial = 2.f * zr * wrow[0] + 2.f * zi * wrow[1] + ez * wrow[2];
        atomicAdd(&s_acc[lane], partial);
    }
    __syncthreads();
    if (tid < ncls) {
        const int b_blk = (int)((blockIdx.x * (blockDim.x >> 5)) / 676);
        atomicAdd(&out[b_blk * ncls + tid], s_acc[tid]);
    }
}

// ============================================================================
extern "C" void kernel_launch(void* const* d_in, const int* in_sizes, int n_in,
                              void* d_out, int out_size) {
    const float* x    = (const float*)d_in[0];   // (B,1,28,28)
    const float* w    = (const float*)d_in[1];   // (42,)
    const float* fc_w = (const float*)d_in[2];   // (ncls, K)
    const float* fc_b = (const float*)d_in[3];   // (ncls,)
    float* out = (float*)d_out;

    const int B      = in_sizes[0] / (28 * 28);
    const int npatch = B * 26 * 26;              // divisible by 4 (676 = 4*169)
    const int ncls   = in_sizes[3];
    const int K      = in_sizes[2] / ncls;

    init_kernel<<<1, 256>>>(w, fc_b, out, ncls, B * ncls);

    const int warps_per_block = 4;               // 676 % 4 == 0 -> block uniform in b
    const int blocks = (npatch + warps_per_block - 1) / warps_per_block;
    qcnn_kernel<<<blocks, warps_per_block * 32>>>(x, fc_w, out, npatch, K, ncls);
}